// round 9
// baseline (speedup 1.0000x reference)
#include <cuda_runtime.h>
#include <cuda_bf16.h>
#include <math.h>

// Problem constants
#define S_LEN 2048
#define HID   4096
#define NHQ   32
#define NHKV  8
#define HD    128
#define QK_SCALE 0.08838834764831845f   // 1/sqrt(128)

// ---------------- scratch (static device arrays; no allocation) -------------
__device__ float g_Q[S_LEN * NHQ * HD];     // 2048 x 4096
__device__ float g_K[S_LEN * NHKV * HD];    // 2048 x 1024
__device__ float g_V[S_LEN * NHKV * HD];    // 2048 x 1024
__device__ float g_CTX[S_LEN * NHQ * HD];   // 2048 x 4096
__device__ float g_cs[S_LEN * 64];          // RoPE cos table
__device__ float g_sn[S_LEN * 64];          // RoPE sin table

// ============================================================================
// RoPE table: inv_freq in double (exact vs reference's fp32 rounding),
// then double range-reduction + fp32 sincos (cheap on GB300's weak FP64 pipe).
// ============================================================================
__global__ void rope_table_kernel(float* __restrict__ cs, float* __restrict__ sn)
{
    int idx = blockIdx.x * blockDim.x + threadIdx.x;
    if (idx >= S_LEN * 64) return;
    int d = idx & 63;
    int s = idx >> 6;
    double inv = pow(10000.0, -(double)d / 64.0);
    double ang = (double)s * inv;
    // reduce to [-pi, pi] in double, then fp32 trig (~1 ulp on reduced arg)
    const double TWO_PI = 6.283185307179586476925286766559;
    double r = ang - TWO_PI * rint(ang * (1.0 / TWO_PI));
    float rf = (float)r;
    float sf, cf;
    sincosf(rf, &sf, &cf);
    cs[idx] = cf;
    sn[idx] = sf;
}

// ============================================================================
// Common TF32 helpers
// ============================================================================
__device__ __forceinline__ void tf32_split(float x, unsigned& h, unsigned& l)
{
    asm("cvt.rna.tf32.f32 %0, %1;" : "=r"(h) : "f"(x));
    float r = x - __uint_as_float(h);
    asm("cvt.rna.tf32.f32 %0, %1;" : "=r"(l) : "f"(r));
}

__device__ __forceinline__ void mma_tf32(float* c,
                                         unsigned a0, unsigned a1, unsigned a2, unsigned a3,
                                         unsigned b0, unsigned b1)
{
    asm volatile(
        "mma.sync.aligned.m16n8k8.row.col.f32.tf32.tf32.f32 "
        "{%0,%1,%2,%3}, {%4,%5,%6,%7}, {%8,%9}, {%0,%1,%2,%3};"
        : "+f"(c[0]), "+f"(c[1]), "+f"(c[2]), "+f"(c[3])
        : "r"(a0), "r"(a1), "r"(a2), "r"(a3), "r"(b0), "r"(b1));
}

// ============================================================================
// TF32 tensor-core GEMM tile worker (3xTF32 precision recovery).
// C[tile] = A[M,K] @ B[K,N] + bias[N], CTA tile 128x128x32, 8 warps.
// TSTR=136: fragment-load bank = (8*qid+grp) mod 32, bijection -> conflict-free.
// Single-barrier double buffering: store(buf); barrier; prefetch; compute(buf).
// ============================================================================
#define TBM 128
#define TBN 128
#define TBK 32
#define TSTR 136   // padded smem stride (floats); conflict-free fragment loads

__device__ __forceinline__
void tf32_gemm_tile(const float* __restrict__ A,
                    const float* __restrict__ B,
                    const float* __restrict__ bias,
                    float* __restrict__ C,
                    int N, int K, int bx, int by, float* sm)
{
    float* As = sm;                       // [2][TBK][TSTR], k-outer
    float* Bs = sm + 2 * TBK * TSTR;      // [2][TBK][TSTR]

    const int tid = threadIdx.x;
    const int lane = tid & 31;
    const int w    = tid >> 5;
    const int grp  = lane >> 2;
    const int qid  = lane & 3;
    const int wm   = (w & 1) * 64;
    const int wn   = (w >> 1) * 32;

    const int arow  = tid >> 1;
    const int acol0 = (tid & 1) * 4;
    const float* Ag = A + (size_t)(by * TBM + arow) * K;
    const int brow  = tid >> 3;
    const int bcol0 = (tid & 7) * 4;
    const float* Bg = B + (size_t)bx * TBN;

    float c[4][4][4];
#pragma unroll
    for (int i = 0; i < 4; i++)
#pragma unroll
        for (int j = 0; j < 4; j++)
#pragma unroll
            for (int q = 0; q < 4; q++) c[i][j][q] = 0.0f;

    // prologue: prefetch tile 0 into registers
    float4 av[4], bv[4];
#pragma unroll
    for (int i = 0; i < 4; i++) {
        av[i] = *(const float4*)(Ag + acol0 + 8 * i);
        bv[i] = *(const float4*)(Bg + (size_t)brow * N + bcol0 + 32 * i);
    }

    int buf = 0;
    for (int k0 = 0; k0 < K; k0 += TBK) {
        // ---- store prefetched tile into smem[buf] ----
        {
            float* An = As + buf * TBK * TSTR;
            float* Bn = Bs + buf * TBK * TSTR;
#pragma unroll
            for (int i = 0; i < 4; i++) {
                int kc = acol0 + 8 * i;
                An[(kc + 0) * TSTR + arow] = av[i].x;
                An[(kc + 1) * TSTR + arow] = av[i].y;
                An[(kc + 2) * TSTR + arow] = av[i].z;
                An[(kc + 3) * TSTR + arow] = av[i].w;
                *(float4*)&Bn[brow * TSTR + bcol0 + 32 * i] = bv[i];
            }
        }
        __syncthreads();   // single barrier per k-tile

        // ---- prefetch next tile ----
        const bool has_next = (k0 + TBK < K);
        if (has_next) {
#pragma unroll
            for (int i = 0; i < 4; i++) {
                av[i] = *(const float4*)(Ag + k0 + TBK + acol0 + 8 * i);
                bv[i] = *(const float4*)(Bg + (size_t)(k0 + TBK + brow) * N + bcol0 + 32 * i);
            }
        }

        // ---- compute from smem[buf] ----
        const float* Ab = As + buf * TBK * TSTR;
        const float* Bb = Bs + buf * TBK * TSTR;
#pragma unroll
        for (int ks = 0; ks < 4; ks++) {
            const int kb = ks * 8;
            unsigned ah[16], al[16];
#pragma unroll
            for (int tm = 0; tm < 4; tm++) {
                int rm = wm + tm * 16 + grp;
                float x0 = Ab[(kb + qid) * TSTR + rm];
                float x1 = Ab[(kb + qid) * TSTR + rm + 8];
                float x2 = Ab[(kb + qid + 4) * TSTR + rm];
                float x3 = Ab[(kb + qid + 4) * TSTR + rm + 8];
                tf32_split(x0, ah[tm * 4 + 0], al[tm * 4 + 0]);
                tf32_split(x1, ah[tm * 4 + 1], al[tm * 4 + 1]);
                tf32_split(x2, ah[tm * 4 + 2], al[tm * 4 + 2]);
                tf32_split(x3, ah[tm * 4 + 3], al[tm * 4 + 3]);
            }
            unsigned bh[8], bl[8];
#pragma unroll
            for (int tn = 0; tn < 4; tn++) {
                int cb = wn + tn * 8 + grp;
                float y0 = Bb[(kb + qid) * TSTR + cb];
                float y1 = Bb[(kb + qid + 4) * TSTR + cb];
                tf32_split(y0, bh[tn * 2 + 0], bl[tn * 2 + 0]);
                tf32_split(y1, bh[tn * 2 + 1], bl[tn * 2 + 1]);
            }
#pragma unroll
            for (int tm = 0; tm < 4; tm++)
#pragma unroll
                for (int tn = 0; tn < 4; tn++) {
                    float* cc = c[tm][tn];
                    mma_tf32(cc, ah[tm*4+0], ah[tm*4+1], ah[tm*4+2], ah[tm*4+3],
                             bh[tn*2+0], bh[tn*2+1]);
                    mma_tf32(cc, ah[tm*4+0], ah[tm*4+1], ah[tm*4+2], ah[tm*4+3],
                             bl[tn*2+0], bl[tn*2+1]);
                    mma_tf32(cc, al[tm*4+0], al[tm*4+1], al[tm*4+2], al[tm*4+3],
                             bh[tn*2+0], bh[tn*2+1]);
                }
        }
        buf ^= 1;
    }

#pragma unroll
    for (int tm = 0; tm < 4; tm++) {
        int r0 = by * TBM + wm + tm * 16 + grp;
        int r1 = r0 + 8;
#pragma unroll
        for (int tn = 0; tn < 4; tn++) {
            int col = bx * TBN + wn + tn * 8 + qid * 2;
            float b0 = bias[col], b1 = bias[col + 1];
            float2 o0 = make_float2(c[tm][tn][0] + b0, c[tm][tn][1] + b1);
            float2 o1 = make_float2(c[tm][tn][2] + b0, c[tm][tn][3] + b1);
            *(float2*)&C[(size_t)r0 * N + col] = o0;
            *(float2*)&C[(size_t)r1 * N + col] = o1;
        }
    }
}

// Fused Q/K/V projection: flattened tile grid.
// Tiles 0..511: Q (16 M-tiles x 32 N-tiles). 512..639: K (16x8). 640..767: V.
__global__ __launch_bounds__(256)
void qkv_proj_kernel(const float* __restrict__ X,
                     const float* __restrict__ Wq, const float* __restrict__ bq, float* __restrict__ Qd,
                     const float* __restrict__ Wk, const float* __restrict__ bk, float* __restrict__ Kd,
                     const float* __restrict__ Wv, const float* __restrict__ bv, float* __restrict__ Vd)
{
    extern __shared__ float sm[];
    int t = blockIdx.x;
    if (t < 512) {
        tf32_gemm_tile(X, Wq, bq, Qd, NHQ * HD, HID, t & 31, t >> 5, sm);
    } else if (t < 640) {
        t -= 512;
        tf32_gemm_tile(X, Wk, bk, Kd, NHKV * HD, HID, t & 7, t >> 3, sm);
    } else {
        t -= 640;
        tf32_gemm_tile(X, Wv, bv, Vd, NHKV * HD, HID, t & 7, t >> 3, sm);
    }
}

// Output projection
__global__ __launch_bounds__(256)
void out_proj_kernel(const float* __restrict__ A,
                     const float* __restrict__ W, const float* __restrict__ b,
                     float* __restrict__ C)
{
    extern __shared__ float sm[];
    tf32_gemm_tile(A, W, b, C, HID, HID, blockIdx.x, blockIdx.y, sm);
}

// ============================================================================
// RoPE (in place), table driven. X layout: [S, nh, 128]. (K only now.)
// ============================================================================
__global__ void rope_kernel(float* __restrict__ X,
                            const float* __restrict__ cs_tab,
                            const float* __restrict__ sn_tab,
                            int nh)
{
    int idx = blockIdx.x * blockDim.x + threadIdx.x;
    int total = S_LEN * nh * 64;
    if (idx >= total) return;
    int d = idx & 63;
    int t = idx >> 6;
    int h = t % nh;
    int s = t / nh;

    float cs = cs_tab[s * 64 + d];
    float sn = sn_tab[s * 64 + d];

    float* base = X + (size_t)s * nh * HD + (size_t)h * HD;
    float x1 = base[d];
    float x2 = base[d + 64];
    base[d]      = x1 * cs - x2 * sn;
    base[d + 64] = x1 * sn + x2 * cs;
}

// ============================================================================
// Tensor-core flash attention, causal, TF32 3-split, fused Q-RoPE.
// CTA = (query tile of 64, head). 256 threads = 8 warps.
// qt = 31 - blockIdx.x  (LPT: heaviest causal tiles scheduled first).
// S-phase: warp w -> rows (w&3)*16, cols (w>>2)*32 of S[64][64].
// PV-phase: warp w -> rows (w&3)*16, dims (w>>2)*64 of O[64][128].
// Q/K/V smem pre-split into interleaved tf32 hi/lo uints (ASTR=264 words).
// ============================================================================
#define ASTR 264
#define APSTR 68

__global__ __launch_bounds__(256, 1)
void attn_tc_kernel(const float* __restrict__ Q,
                    const float* __restrict__ K,
                    const float* __restrict__ V,
                    const float* __restrict__ cs_tab,
                    const float* __restrict__ sn_tab,
                    float* __restrict__ CTX)
{
    extern __shared__ unsigned usm[];
    unsigned* Qhl = usm;                    // 64*264 uints
    unsigned* Khl = Qhl + 64 * ASTR;
    unsigned* Vhl = Khl + 64 * ASTR;
    float* Ps      = (float*)(Vhl + 64 * ASTR);   // 64*68
    float* red_max = Ps + 64 * APSTR;             // [2][64]
    float* red_sum = red_max + 128;               // [2][64]

    const int h   = blockIdx.y;
    const int gkv = h >> 2;
    const int qt  = (int)gridDim.x - 1 - (int)blockIdx.x;   // LPT ordering
    const int tid = threadIdx.x;
    const int lane = tid & 31;
    const int w    = tid >> 5;
    const int grp  = lane >> 2;
    const int qid  = lane & 3;
    const int wrow = (w & 3) * 16;
    const int wcol = w >> 2;          // 0 or 1
    const int wc   = wcol * 32;       // S col offset
    const int wd   = wcol * 64;       // O dim offset

    // K/V tile-load coordinates (8 strided row-steps, full 128 dims)
    const int lr  = tid >> 5;         // base row 0..7 (+8 per step)
    const int lc4 = (tid & 31) * 4;   // col group 0..124

    // ---- load Q tile: RoPE-rotate, scale, split, interleave ----
    {
        const int qr0 = tid >> 4;          // 0..15 (+16 per step)
        const int dc4 = (tid & 15) * 4;    // 0..60
#pragma unroll
        for (int ii = 0; ii < 4; ii++) {
            int r = qr0 + ii * 16;
            int srow = qt * 64 + r;
            const float* qb = &Q[(size_t)srow * (NHQ * HD) + h * HD];
            float4 x1 = *(const float4*)&qb[dc4];
            float4 x2 = *(const float4*)&qb[dc4 + 64];
            float4 cs = *(const float4*)&cs_tab[srow * 64 + dc4];
            float4 sn = *(const float4*)&sn_tab[srow * 64 + dc4];
            float lo4[4] = {x1.x * cs.x - x2.x * sn.x, x1.y * cs.y - x2.y * sn.y,
                            x1.z * cs.z - x2.z * sn.z, x1.w * cs.w - x2.w * sn.w};
            float hi4[4] = {x1.x * sn.x + x2.x * cs.x, x1.y * sn.y + x2.y * cs.y,
                            x1.z * sn.z + x2.z * cs.z, x1.w * sn.w + x2.w * cs.w};
#pragma unroll
            for (int j = 0; j < 4; j++) {
                unsigned hi, lo;
                tf32_split(lo4[j] * QK_SCALE, hi, lo);
                Qhl[r * ASTR + 2 * (dc4 + j)]          = hi;
                Qhl[r * ASTR + 2 * (dc4 + j) + 1]      = lo;
                tf32_split(hi4[j] * QK_SCALE, hi, lo);
                Qhl[r * ASTR + 2 * (dc4 + 64 + j)]     = hi;
                Qhl[r * ASTR + 2 * (dc4 + 64 + j) + 1] = lo;
            }
        }
    }

    float m0 = -1e30f, m1 = -1e30f, l0 = 0.0f, l1 = 0.0f;
    float acc[8][4];
#pragma unroll
    for (int tn = 0; tn < 8; tn++)
#pragma unroll
        for (int q = 0; q < 4; q++) acc[tn][q] = 0.0f;

    for (int kb = 0; kb <= qt; kb++) {
        // ---- prefetch K,V tile into registers BEFORE the barrier ----
        float4 kreg[8], vreg[8];
#pragma unroll
        for (int ii = 0; ii < 8; ii++) {
            int r = lr + ii * 8;
            size_t src = (size_t)(kb * 64 + r) * (NHKV * HD) + gkv * HD + lc4;
            kreg[ii] = *(const float4*)&K[src];
            vreg[ii] = *(const float4*)&V[src];
        }
        __syncthreads();   // prev iter done reading K/V/Ps (Q ready first iter)
        // ---- split & store to smem ----
#pragma unroll
        for (int ii = 0; ii < 8; ii++) {
            int r = lr + ii * 8;
            float kx[4] = {kreg[ii].x, kreg[ii].y, kreg[ii].z, kreg[ii].w};
            float vx[4] = {vreg[ii].x, vreg[ii].y, vreg[ii].z, vreg[ii].w};
#pragma unroll
            for (int j = 0; j < 4; j++) {
                unsigned hi, lo;
                tf32_split(kx[j], hi, lo);
                Khl[r * ASTR + 2 * (lc4 + j)]     = hi;
                Khl[r * ASTR + 2 * (lc4 + j) + 1] = lo;
                tf32_split(vx[j], hi, lo);
                Vhl[r * ASTR + 2 * (lc4 + j)]     = hi;
                Vhl[r * ASTR + 2 * (lc4 + j) + 1] = lo;
            }
        }
        __syncthreads();

        // ---- S = Q K^T (warp tile 16x32) ----
        float s[4][4];
#pragma unroll
        for (int tn = 0; tn < 4; tn++)
#pragma unroll
            for (int q = 0; q < 4; q++) s[tn][q] = 0.0f;

#pragma unroll 4
        for (int k0 = 0; k0 < HD; k0 += 8) {
            uint2 a0 = *(const uint2*)&Qhl[(wrow + grp)     * ASTR + 2 * (k0 + qid)];
            uint2 a1 = *(const uint2*)&Qhl[(wrow + grp + 8) * ASTR + 2 * (k0 + qid)];
            uint2 a2 = *(const uint2*)&Qhl[(wrow + grp)     * ASTR + 2 * (k0 + qid + 4)];
            uint2 a3 = *(const uint2*)&Qhl[(wrow + grp + 8) * ASTR + 2 * (k0 + qid + 4)];
#pragma unroll
            for (int tn = 0; tn < 4; tn++) {
                uint2 b0 = *(const uint2*)&Khl[(wc + tn * 8 + grp) * ASTR + 2 * (k0 + qid)];
                uint2 b1 = *(const uint2*)&Khl[(wc + tn * 8 + grp) * ASTR + 2 * (k0 + qid + 4)];
                mma_tf32(s[tn], a0.x, a1.x, a2.x, a3.x, b0.x, b1.x);
                mma_tf32(s[tn], a0.x, a1.x, a2.x, a3.x, b0.y, b1.y);
                mma_tf32(s[tn], a0.y, a1.y, a2.y, a3.y, b0.x, b1.x);
            }
        }

        // ---- causal mask on diagonal block ----
        if (kb == qt) {
            int lr0 = wrow + grp, lr1 = lr0 + 8;
#pragma unroll
            for (int tn = 0; tn < 4; tn++) {
                int lc0 = wc + tn * 8 + qid * 2;
                int lc1 = lc0 + 1;
                if (lc0 > lr0) s[tn][0] = -1e30f;
                if (lc1 > lr0) s[tn][1] = -1e30f;
                if (lc0 > lr1) s[tn][2] = -1e30f;
                if (lc1 > lr1) s[tn][3] = -1e30f;
            }
        }

        // ---- row max (local + quad shuffle + cross-warp-pair) ----
        float rm0 = -1e30f, rm1 = -1e30f;
#pragma unroll
        for (int tn = 0; tn < 4; tn++) {
            rm0 = fmaxf(rm0, fmaxf(s[tn][0], s[tn][1]));
            rm1 = fmaxf(rm1, fmaxf(s[tn][2], s[tn][3]));
        }
        rm0 = fmaxf(rm0, __shfl_xor_sync(0xffffffffu, rm0, 1));
        rm0 = fmaxf(rm0, __shfl_xor_sync(0xffffffffu, rm0, 2));
        rm1 = fmaxf(rm1, __shfl_xor_sync(0xffffffffu, rm1, 1));
        rm1 = fmaxf(rm1, __shfl_xor_sync(0xffffffffu, rm1, 2));
        if (qid == 0) {
            red_max[wcol * 64 + wrow + grp]     = rm0;
            red_max[wcol * 64 + wrow + grp + 8] = rm1;
        }
        __syncthreads();
        float om0 = red_max[(wcol ^ 1) * 64 + wrow + grp];
        float om1 = red_max[(wcol ^ 1) * 64 + wrow + grp + 8];
        float mn0 = fmaxf(m0, fmaxf(rm0, om0));
        float mn1 = fmaxf(m1, fmaxf(rm1, om1));
        float sc0 = __expf(m0 - mn0);
        float sc1 = __expf(m1 - mn1);

        // ---- probs + row sums; publish P ----
        float rs0 = 0.0f, rs1 = 0.0f;
#pragma unroll
        for (int tn = 0; tn < 4; tn++) {
            s[tn][0] = __expf(s[tn][0] - mn0);
            s[tn][1] = __expf(s[tn][1] - mn0);
            s[tn][2] = __expf(s[tn][2] - mn1);
            s[tn][3] = __expf(s[tn][3] - mn1);
            rs0 += s[tn][0] + s[tn][1];
            rs1 += s[tn][2] + s[tn][3];
            *(float2*)&Ps[(wrow + grp)     * APSTR + wc + tn * 8 + qid * 2] =
                make_float2(s[tn][0], s[tn][1]);
            *(float2*)&Ps[(wrow + grp + 8) * APSTR + wc + tn * 8 + qid * 2] =
                make_float2(s[tn][2], s[tn][3]);
        }
        rs0 += __shfl_xor_sync(0xffffffffu, rs0, 1);
        rs0 += __shfl_xor_sync(0xffffffffu, rs0, 2);
        rs1 += __shfl_xor_sync(0xffffffffu, rs1, 1);
        rs1 += __shfl_xor_sync(0xffffffffu, rs1, 2);
        if (qid == 0) {
            red_sum[wcol * 64 + wrow + grp]     = rs0;
            red_sum[wcol * 64 + wrow + grp + 8] = rs1;
        }
        __syncthreads();
        float os0 = red_sum[(wcol ^ 1) * 64 + wrow + grp];
        float os1 = red_sum[(wcol ^ 1) * 64 + wrow + grp + 8];
        l0 = l0 * sc0 + rs0 + os0;
        l1 = l1 * sc1 + rs1 + os1;
        m0 = mn0;
        m1 = mn1;
#pragma unroll
        for (int tn = 0; tn < 8; tn++) {
            acc[tn][0] *= sc0; acc[tn][1] *= sc0;
            acc[tn][2] *= sc1; acc[tn][3] *= sc1;
        }

        // ---- O += P @ V (warp tile 16 rows x 64 dims) ----
#pragma unroll 2
        for (int kk = 0; kk < 64; kk += 8) {
            float p0 = Ps[(wrow + grp)     * APSTR + kk + qid];
            float p1 = Ps[(wrow + grp + 8) * APSTR + kk + qid];
            float p2 = Ps[(wrow + grp)     * APSTR + kk + qid + 4];
            float p3 = Ps[(wrow + grp + 8) * APSTR + kk + qid + 4];
            unsigned ph0, pl0, ph1, pl1, ph2, pl2, ph3, pl3;
            tf32_split(p0, ph0, pl0);
            tf32_split(p1, ph1, pl1);
            tf32_split(p2, ph2, pl2);
            tf32_split(p3, ph3, pl3);
#pragma unroll
            for (int tn = 0; tn < 8; tn++) {
                uint2 b0 = *(const uint2*)&Vhl[(kk + qid)     * ASTR + 2 * (wd + tn * 8 + grp)];
                uint2 b1 = *(const uint2*)&Vhl[(kk + qid + 4) * ASTR + 2 * (wd + tn * 8 + grp)];
                mma_tf32(acc[tn], ph0, ph1, ph2, ph3, b0.x, b1.x);
                mma_tf32(acc[tn], ph0, ph1, ph2, ph3, b0.y, b1.y);
                mma_tf32(acc[tn], pl0, pl1, pl2, pl3, b0.x, b1.x);
            }
        }
    }

    // ---- epilogue ----
    float il0 = 1.0f / l0, il1 = 1.0f / l1;
    int row0 = qt * 64 + wrow + grp;
    int row1 = row0 + 8;
#pragma unroll
    for (int tn = 0; tn < 8; tn++) {
        int col = h * HD + wd + tn * 8 + qid * 2;
        *(float2*)&CTX[(size_t)row0 * (NHQ * HD) + col] =
            make_float2(acc[tn][0] * il0, acc[tn][1] * il0);
        *(float2*)&CTX[(size_t)row1 * (NHQ * HD) + col] =
            make_float2(acc[tn][2] * il1, acc[tn][3] * il1);
    }
}

// ============================================================================
// launch
// ============================================================================
extern "C" void kernel_launch(void* const* d_in, const int* in_sizes, int n_in,
                              void* d_out, int out_size)
{
    const float* X  = (const float*)d_in[0];
    const float* Wq = (const float*)d_in[1];
    const float* bq = (const float*)d_in[2];
    const float* Wk = (const float*)d_in[3];
    const float* bk = (const float*)d_in[4];
    const float* Wv = (const float*)d_in[5];
    const float* bv = (const float*)d_in[6];
    const float* Wo = (const float*)d_in[7];
    const float* bo = (const float*)d_in[8];
    float* out = (float*)d_out;

    float *Qd, *Kd, *Vd, *CTXd, *CSd, *SNd;
    cudaGetSymbolAddress((void**)&Qd,   g_Q);
    cudaGetSymbolAddress((void**)&Kd,   g_K);
    cudaGetSymbolAddress((void**)&Vd,   g_V);
    cudaGetSymbolAddress((void**)&CTXd, g_CTX);
    cudaGetSymbolAddress((void**)&CSd,  g_cs);
    cudaGetSymbolAddress((void**)&SNd,  g_sn);

    const int gemm_smem = 2 * 2 * TBK * TSTR * (int)sizeof(float);  // 69632 B
    cudaFuncSetAttribute(qkv_proj_kernel,
                         cudaFuncAttributeMaxDynamicSharedMemorySize, gemm_smem);
    cudaFuncSetAttribute(out_proj_kernel,
                         cudaFuncAttributeMaxDynamicSharedMemorySize, gemm_smem);

    // RoPE table
    rope_table_kernel<<<(S_LEN * 64 + 255) / 256, 256>>>(CSd, SNd);

    // Fused QKV projections: 512 Q-tiles + 128 K-tiles + 128 V-tiles
    qkv_proj_kernel<<<768, 256, gemm_smem>>>(X, Wq, bq, Qd, Wk, bk, Kd, Wv, bv, Vd);

    // RoPE on K only (Q rope is fused into attention load)
    {
        int tk = S_LEN * NHKV * 64;
        rope_kernel<<<(tk + 255) / 256, 256>>>(Kd, CSd, SNd, NHKV);
    }

    // attention (tensor-core, fused Q-RoPE, LPT tile order)
    {
        int smem = (3 * 64 * ASTR) * 4 + (64 * APSTR) * 4 + 2 * 128 * 4;  // 221184 B
        cudaFuncSetAttribute(attn_tc_kernel,
                             cudaFuncAttributeMaxDynamicSharedMemorySize, smem);
        dim3 ga(S_LEN / 64, NHQ);
        attn_tc_kernel<<<ga, 256, smem>>>(Qd, Kd, Vd, CSd, SNd, CTXd);
    }

    // output projection
    {
        dim3 go(HID / TBN, S_LEN / TBM);
        out_proj_kernel<<<go, 256, gemm_smem>>>(CTXd, Wo, bo, out);
    }
}

// round 11
// speedup vs baseline: 1.5239x; 1.5239x over previous
#include <cuda_runtime.h>
#include <cuda_bf16.h>
#include <math.h>

// Problem constants
#define S_LEN 2048
#define HID   4096
#define NHQ   32
#define NHKV  8
#define HD    128
#define QK_SCALE 0.08838834764831845f   // 1/sqrt(128)

// ---------------- scratch (static device arrays; no allocation) -------------
__device__ float g_Q[S_LEN * NHQ * HD];     // 2048 x 4096
__device__ float g_K[S_LEN * NHKV * HD];    // 2048 x 1024
__device__ float g_V[S_LEN * NHKV * HD];    // 2048 x 1024
__device__ float g_CTX[S_LEN * NHQ * HD];   // 2048 x 4096
__device__ float g_cs[S_LEN * 64];          // RoPE cos table
__device__ float g_sn[S_LEN * 64];          // RoPE sin table

// bf16 hi/lo pre-split operands
__device__ __nv_bfloat16 g_Xhi[S_LEN * HID],        g_Xlo[S_LEN * HID];
__device__ __nv_bfloat16 g_CTXhi[S_LEN * HID],      g_CTXlo[S_LEN * HID];
__device__ __nv_bfloat16 g_WqhiT[HID * (NHQ*HD)],   g_WqloT[HID * (NHQ*HD)];    // [N][K]
__device__ __nv_bfloat16 g_WkhiT[HID * (NHKV*HD)],  g_WkloT[HID * (NHKV*HD)];
__device__ __nv_bfloat16 g_WvhiT[HID * (NHKV*HD)],  g_WvloT[HID * (NHKV*HD)];
__device__ __nv_bfloat16 g_WohiT[(NHQ*HD) * HID],   g_WoloT[(NHQ*HD) * HID];

// ============================================================================
// RoPE table: inv_freq in double; double range-reduction + fp32 sincos.
// ============================================================================
__global__ void rope_table_kernel(float* __restrict__ cs, float* __restrict__ sn)
{
    int idx = blockIdx.x * blockDim.x + threadIdx.x;
    if (idx >= S_LEN * 64) return;
    int d = idx & 63;
    int s = idx >> 6;
    double inv = pow(10000.0, -(double)d / 64.0);
    double ang = (double)s * inv;
    const double TWO_PI = 6.283185307179586476925286766559;
    double r = ang - TWO_PI * rint(ang * (1.0 / TWO_PI));
    float sf, cf;
    sincosf((float)r, &sf, &cf);
    cs[idx] = cf;
    sn[idx] = sf;
}

// ============================================================================
// bf16 hi/lo split helpers
// ============================================================================
__device__ __forceinline__ void bf16_split(float x, __nv_bfloat16& h, __nv_bfloat16& l)
{
    h = __float2bfloat16(x);
    l = __float2bfloat16(x - __bfloat162float(h));
}

// Plain split: arr [R][C] fp32 -> hi, lo bf16 same layout. n4 = elems/4.
__global__ void split_plain_kernel(const float* __restrict__ in,
                                   __nv_bfloat16* __restrict__ hi,
                                   __nv_bfloat16* __restrict__ lo, int n4)
{
    int i = blockIdx.x * blockDim.x + threadIdx.x;
    if (i >= n4) return;
    float4 x = ((const float4*)in)[i];
    __nv_bfloat16 h0, h1, h2, h3, l0, l1, l2, l3;
    bf16_split(x.x, h0, l0); bf16_split(x.y, h1, l1);
    bf16_split(x.z, h2, l2); bf16_split(x.w, h3, l3);
    __nv_bfloat162* hp = (__nv_bfloat162*)hi;
    __nv_bfloat162* lp = (__nv_bfloat162*)lo;
    hp[2*i]   = __nv_bfloat162(h0, h1);
    hp[2*i+1] = __nv_bfloat162(h2, h3);
    lp[2*i]   = __nv_bfloat162(l0, l1);
    lp[2*i+1] = __nv_bfloat162(l2, l3);
}

// Transpose-split: W fp32 [Kdim][Ndim] -> hiT, loT bf16 [Ndim][Kdim].
// 32x32 smem tile, 256 threads.
__global__ void transpose_split_kernel(const float* __restrict__ W,
                                       __nv_bfloat16* __restrict__ hiT,
                                       __nv_bfloat16* __restrict__ loT,
                                       int Kdim, int Ndim)
{
    __shared__ float t[32][33];
    int n0 = blockIdx.x * 32, k0 = blockIdx.y * 32;
    int tx = threadIdx.x & 31, ty = threadIdx.x >> 5;   // ty 0..7
#pragma unroll
    for (int j = 0; j < 32; j += 8)
        t[ty + j][tx] = W[(size_t)(k0 + ty + j) * Ndim + n0 + tx];
    __syncthreads();
#pragma unroll
    for (int j = 0; j < 32; j += 8) {
        float x = t[tx][ty + j];
        __nv_bfloat16 h, l;
        bf16_split(x, h, l);
        size_t o = (size_t)(n0 + ty + j) * Kdim + k0 + tx;
        hiT[o] = h;
        loT[o] = l;
    }
}

// ============================================================================
// TF32 helpers (attention only)
// ============================================================================
__device__ __forceinline__ void tf32_split(float x, unsigned& h, unsigned& l)
{
    asm("cvt.rna.tf32.f32 %0, %1;" : "=r"(h) : "f"(x));
    float r = x - __uint_as_float(h);
    asm("cvt.rna.tf32.f32 %0, %1;" : "=r"(l) : "f"(r));
}

__device__ __forceinline__ void mma_tf32(float* c,
                                         unsigned a0, unsigned a1, unsigned a2, unsigned a3,
                                         unsigned b0, unsigned b1)
{
    asm volatile(
        "mma.sync.aligned.m16n8k8.row.col.f32.tf32.tf32.f32 "
        "{%0,%1,%2,%3}, {%4,%5,%6,%7}, {%8,%9}, {%0,%1,%2,%3};"
        : "+f"(c[0]), "+f"(c[1]), "+f"(c[2]), "+f"(c[3])
        : "r"(a0), "r"(a1), "r"(a2), "r"(a3), "r"(b0), "r"(b1));
}

__device__ __forceinline__ void mma_bf16(float* c,
                                         unsigned a0, unsigned a1, unsigned a2, unsigned a3,
                                         unsigned b0, unsigned b1)
{
    asm volatile(
        "mma.sync.aligned.m16n8k16.row.col.f32.bf16.bf16.f32 "
        "{%0,%1,%2,%3}, {%4,%5,%6,%7}, {%8,%9}, {%0,%1,%2,%3};"
        : "+f"(c[0]), "+f"(c[1]), "+f"(c[2]), "+f"(c[3])
        : "r"(a0), "r"(a1), "r"(a2), "r"(a3), "r"(b0), "r"(b1));
}

// ============================================================================
// bf16x3 GEMM tile worker with pre-split operands.
// C[tile] = Ahi*Bhi + Ahi*Blo + Alo*Bhi + bias.
// A: [M][K] bf16 (hi/lo). B: [N][K] bf16 (transposed hi/lo).
// CTA tile 128x128x32, 8 warps, warp tile 64x32.
// smem row = 32 bf16 = 16 words, padded to GBSTR=20 words:
//   frag-load bank = (20*grp + qid) mod 32 -> bijection, conflict-free.
// Stage: Ahi@0, Alo@2560, Bhi@5120, Blo@7680 (words); stage = 10240 words.
// ============================================================================
#define GBSTR 20
#define GSTAGE 10240

__device__ __forceinline__
void bf16_gemm_tile(const __nv_bfloat16* __restrict__ Ahi,
                    const __nv_bfloat16* __restrict__ Alo,
                    const __nv_bfloat16* __restrict__ BhiT,
                    const __nv_bfloat16* __restrict__ BloT,
                    const float* __restrict__ bias,
                    float* __restrict__ C,
                    int N, int K, int bx, int by, unsigned* sm)
{
    const int tid = threadIdx.x;
    const int lane = tid & 31;
    const int w    = tid >> 5;
    const int grp  = lane >> 2;
    const int qid  = lane & 3;
    const int wm   = (w & 1) * 64;
    const int wn   = (w >> 1) * 32;

    // loader: thread handles rows lr, lr+64; quad lq (8 bf16 = 1 uint4 each)
    const int lr = tid >> 2;      // 0..63
    const int lq = tid & 3;       // 0..3
    const int K8 = K >> 3;        // row stride in uint4

    const uint4* A4h = (const uint4*)Ahi  + (size_t)(by * 128) * K8;
    const uint4* A4l = (const uint4*)Alo  + (size_t)(by * 128) * K8;
    const uint4* B4h = (const uint4*)BhiT + (size_t)(bx * 128) * K8;
    const uint4* B4l = (const uint4*)BloT + (size_t)(bx * 128) * K8;

    float c[4][4][4];
#pragma unroll
    for (int i = 0; i < 4; i++)
#pragma unroll
        for (int j = 0; j < 4; j++)
#pragma unroll
            for (int q = 0; q < 4; q++) c[i][j][q] = 0.0f;

    // prologue prefetch (k-tile 0): 8 uint4
    uint4 pah[2], pal[2], pbh[2], pbl[2];
#pragma unroll
    for (int s = 0; s < 2; s++) {
        size_t off = (size_t)(lr + 64 * s) * K8 + lq;
        pah[s] = A4h[off]; pal[s] = A4l[off];
        pbh[s] = B4h[off]; pbl[s] = B4l[off];
    }

    int buf = 0;
    for (int k0 = 0; k0 < K; k0 += 32) {
        // ---- store prefetched tiles into smem[buf] ----
        {
            unsigned* st = sm + buf * GSTAGE;
#pragma unroll
            for (int s = 0; s < 2; s++) {
                int wo = (lr + 64 * s) * GBSTR + lq * 4;
                *(uint4*)(st + wo)        = pah[s];
                *(uint4*)(st + wo + 2560) = pal[s];
                *(uint4*)(st + wo + 5120) = pbh[s];
                *(uint4*)(st + wo + 7680) = pbl[s];
            }
        }
        __syncthreads();   // single barrier per k-tile

        // ---- prefetch next k-tile ----
        if (k0 + 32 < K) {
            int kb = (k0 + 32) >> 3;
#pragma unroll
            for (int s = 0; s < 2; s++) {
                size_t off = (size_t)(lr + 64 * s) * K8 + kb + lq;
                pah[s] = A4h[off]; pal[s] = A4l[off];
                pbh[s] = B4h[off]; pbl[s] = B4l[off];
            }
        }

        // ---- compute: 2 k-steps of 16 ----
        const unsigned* Ah = sm + buf * GSTAGE;
        const unsigned* Al = Ah + 2560;
        const unsigned* Bh = Ah + 5120;
        const unsigned* Bl = Ah + 7680;
#pragma unroll
        for (int ks = 0; ks < 2; ks++) {
            const int kw = ks * 8;
            unsigned ah[16], al[16];
#pragma unroll
            for (int tm = 0; tm < 4; tm++) {
                int r0 = (wm + tm * 16 + grp) * GBSTR + kw + qid;
                int r1 = r0 + 8 * GBSTR;
                ah[tm*4+0] = Ah[r0];     ah[tm*4+1] = Ah[r1];
                ah[tm*4+2] = Ah[r0 + 4]; ah[tm*4+3] = Ah[r1 + 4];
                al[tm*4+0] = Al[r0];     al[tm*4+1] = Al[r1];
                al[tm*4+2] = Al[r0 + 4]; al[tm*4+3] = Al[r1 + 4];
            }
            unsigned bh[8], bl[8];
#pragma unroll
            for (int tn = 0; tn < 4; tn++) {
                int cn = (wn + tn * 8 + grp) * GBSTR + kw + qid;
                bh[tn*2+0] = Bh[cn]; bh[tn*2+1] = Bh[cn + 4];
                bl[tn*2+0] = Bl[cn]; bl[tn*2+1] = Bl[cn + 4];
            }
#pragma unroll
            for (int tm = 0; tm < 4; tm++)
#pragma unroll
                for (int tn = 0; tn < 4; tn++) {
                    float* cc = c[tm][tn];
                    mma_bf16(cc, ah[tm*4+0], ah[tm*4+1], ah[tm*4+2], ah[tm*4+3],
                             bh[tn*2+0], bh[tn*2+1]);
                    mma_bf16(cc, ah[tm*4+0], ah[tm*4+1], ah[tm*4+2], ah[tm*4+3],
                             bl[tn*2+0], bl[tn*2+1]);
                    mma_bf16(cc, al[tm*4+0], al[tm*4+1], al[tm*4+2], al[tm*4+3],
                             bh[tn*2+0], bh[tn*2+1]);
                }
        }
        buf ^= 1;
    }

    // ---- epilogue with bias ----
#pragma unroll
    for (int tm = 0; tm < 4; tm++) {
        int r0 = by * 128 + wm + tm * 16 + grp;
        int r1 = r0 + 8;
#pragma unroll
        for (int tn = 0; tn < 4; tn++) {
            int col = bx * 128 + wn + tn * 8 + qid * 2;
            float b0 = bias[col], b1 = bias[col + 1];
            float2 o0 = make_float2(c[tm][tn][0] + b0, c[tm][tn][1] + b1);
            float2 o1 = make_float2(c[tm][tn][2] + b0, c[tm][tn][3] + b1);
            *(float2*)&C[(size_t)r0 * N + col] = o0;
            *(float2*)&C[(size_t)r1 * N + col] = o1;
        }
    }
}

// Fused Q/K/V projection: flattened tile grid (0..511 Q, 512..639 K, 640..767 V)
__global__ __launch_bounds__(256)
void qkv_proj_kernel(const float* __restrict__ bq, float* __restrict__ Qd,
                     const float* __restrict__ bk, float* __restrict__ Kd,
                     const float* __restrict__ bv, float* __restrict__ Vd)
{
    extern __shared__ unsigned smu[];
    int t = blockIdx.x;
    if (t < 512) {
        bf16_gemm_tile(g_Xhi, g_Xlo, g_WqhiT, g_WqloT, bq, Qd,
                       NHQ * HD, HID, t & 31, t >> 5, smu);
    } else if (t < 640) {
        t -= 512;
        bf16_gemm_tile(g_Xhi, g_Xlo, g_WkhiT, g_WkloT, bk, Kd,
                       NHKV * HD, HID, t & 7, t >> 3, smu);
    } else {
        t -= 640;
        bf16_gemm_tile(g_Xhi, g_Xlo, g_WvhiT, g_WvloT, bv, Vd,
                       NHKV * HD, HID, t & 7, t >> 3, smu);
    }
}

// Output projection
__global__ __launch_bounds__(256)
void out_proj_kernel(const float* __restrict__ b, float* __restrict__ C)
{
    extern __shared__ unsigned smu[];
    bf16_gemm_tile(g_CTXhi, g_CTXlo, g_WohiT, g_WoloT, b, C,
                   HID, HID, blockIdx.x, blockIdx.y, smu);
}

// ============================================================================
// RoPE (in place), table driven. X layout: [S, nh, 128]. (K only.)
// ============================================================================
__global__ void rope_kernel(float* __restrict__ X,
                            const float* __restrict__ cs_tab,
                            const float* __restrict__ sn_tab,
                            int nh)
{
    int idx = blockIdx.x * blockDim.x + threadIdx.x;
    int total = S_LEN * nh * 64;
    if (idx >= total) return;
    int d = idx & 63;
    int t = idx >> 6;
    int h = t % nh;
    int s = t / nh;

    float cs = cs_tab[s * 64 + d];
    float sn = sn_tab[s * 64 + d];

    float* base = X + (size_t)s * nh * HD + (size_t)h * HD;
    float x1 = base[d];
    float x2 = base[d + 64];
    base[d]      = x1 * cs - x2 * sn;
    base[d + 64] = x1 * sn + x2 * cs;
}

// ============================================================================
// Tensor-core flash attention (byte-identical to the PASSING round-9 kernel):
// causal, TF32 3-split, fused Q-RoPE, LPT tile order.
// ============================================================================
#define ASTR 264
#define APSTR 68

__global__ __launch_bounds__(256, 1)
void attn_tc_kernel(const float* __restrict__ Q,
                    const float* __restrict__ K,
                    const float* __restrict__ V,
                    const float* __restrict__ cs_tab,
                    const float* __restrict__ sn_tab,
                    float* __restrict__ CTX)
{
    extern __shared__ unsigned usm[];
    unsigned* Qhl = usm;
    unsigned* Khl = Qhl + 64 * ASTR;
    unsigned* Vhl = Khl + 64 * ASTR;
    float* Ps      = (float*)(Vhl + 64 * ASTR);
    float* red_max = Ps + 64 * APSTR;
    float* red_sum = red_max + 128;

    const int h   = blockIdx.y;
    const int gkv = h >> 2;
    const int qt  = (int)gridDim.x - 1 - (int)blockIdx.x;   // LPT
    const int tid = threadIdx.x;
    const int lane = tid & 31;
    const int w    = tid >> 5;
    const int grp  = lane >> 2;
    const int qid  = lane & 3;
    const int wrow = (w & 3) * 16;
    const int wcol = w >> 2;
    const int wc   = wcol * 32;
    const int wd   = wcol * 64;

    const int lr  = tid >> 5;
    const int lc4 = (tid & 31) * 4;

    {
        const int qr0 = tid >> 4;
        const int dc4 = (tid & 15) * 4;
#pragma unroll
        for (int ii = 0; ii < 4; ii++) {
            int r = qr0 + ii * 16;
            int srow = qt * 64 + r;
            const float* qb = &Q[(size_t)srow * (NHQ * HD) + h * HD];
            float4 x1 = *(const float4*)&qb[dc4];
            float4 x2 = *(const float4*)&qb[dc4 + 64];
            float4 cs = *(const float4*)&cs_tab[srow * 64 + dc4];
            float4 sn = *(const float4*)&sn_tab[srow * 64 + dc4];
            float lo4[4] = {x1.x * cs.x - x2.x * sn.x, x1.y * cs.y - x2.y * sn.y,
                            x1.z * cs.z - x2.z * sn.z, x1.w * cs.w - x2.w * sn.w};
            float hi4[4] = {x1.x * sn.x + x2.x * cs.x, x1.y * sn.y + x2.y * cs.y,
                            x1.z * sn.z + x2.z * cs.z, x1.w * sn.w + x2.w * cs.w};
#pragma unroll
            for (int j = 0; j < 4; j++) {
                unsigned hi, lo;
                tf32_split(lo4[j] * QK_SCALE, hi, lo);
                Qhl[r * ASTR + 2 * (dc4 + j)]          = hi;
                Qhl[r * ASTR + 2 * (dc4 + j) + 1]      = lo;
                tf32_split(hi4[j] * QK_SCALE, hi, lo);
                Qhl[r * ASTR + 2 * (dc4 + 64 + j)]     = hi;
                Qhl[r * ASTR + 2 * (dc4 + 64 + j) + 1] = lo;
            }
        }
    }

    float m0 = -1e30f, m1 = -1e30f, l0 = 0.0f, l1 = 0.0f;
    float acc[8][4];
#pragma unroll
    for (int tn = 0; tn < 8; tn++)
#pragma unroll
        for (int q = 0; q < 4; q++) acc[tn][q] = 0.0f;

    for (int kb = 0; kb <= qt; kb++) {
        float4 kreg[8], vreg[8];
#pragma unroll
        for (int ii = 0; ii < 8; ii++) {
            int r = lr + ii * 8;
            size_t src = (size_t)(kb * 64 + r) * (NHKV * HD) + gkv * HD + lc4;
            kreg[ii] = *(const float4*)&K[src];
            vreg[ii] = *(const float4*)&V[src];
        }
        __syncthreads();
#pragma unroll
        for (int ii = 0; ii < 8; ii++) {
            int r = lr + ii * 8;
            float kx[4] = {kreg[ii].x, kreg[ii].y, kreg[ii].z, kreg[ii].w};
            float vx[4] = {vreg[ii].x, vreg[ii].y, vreg[ii].z, vreg[ii].w};
#pragma unroll
            for (int j = 0; j < 4; j++) {
                unsigned hi, lo;
                tf32_split(kx[j], hi, lo);
                Khl[r * ASTR + 2 * (lc4 + j)]     = hi;
                Khl[r * ASTR + 2 * (lc4 + j) + 1] = lo;
                tf32_split(vx[j], hi, lo);
                Vhl[r * ASTR + 2 * (lc4 + j)]     = hi;
                Vhl[r * ASTR + 2 * (lc4 + j) + 1] = lo;
            }
        }
        __syncthreads();

        float s[4][4];
#pragma unroll
        for (int tn = 0; tn < 4; tn++)
#pragma unroll
            for (int q = 0; q < 4; q++) s[tn][q] = 0.0f;

#pragma unroll 4
        for (int k0 = 0; k0 < HD; k0 += 8) {
            uint2 a0 = *(const uint2*)&Qhl[(wrow + grp)     * ASTR + 2 * (k0 + qid)];
            uint2 a1 = *(const uint2*)&Qhl[(wrow + grp + 8) * ASTR + 2 * (k0 + qid)];
            uint2 a2 = *(const uint2*)&Qhl[(wrow + grp)     * ASTR + 2 * (k0 + qid + 4)];
            uint2 a3 = *(const uint2*)&Qhl[(wrow + grp + 8) * ASTR + 2 * (k0 + qid + 4)];
#pragma unroll
            for (int tn = 0; tn < 4; tn++) {
                uint2 b0 = *(const uint2*)&Khl[(wc + tn * 8 + grp) * ASTR + 2 * (k0 + qid)];
                uint2 b1 = *(const uint2*)&Khl[(wc + tn * 8 + grp) * ASTR + 2 * (k0 + qid + 4)];
                mma_tf32(s[tn], a0.x, a1.x, a2.x, a3.x, b0.x, b1.x);
                mma_tf32(s[tn], a0.x, a1.x, a2.x, a3.x, b0.y, b1.y);
                mma_tf32(s[tn], a0.y, a1.y, a2.y, a3.y, b0.x, b1.x);
            }
        }

        if (kb == qt) {
            int lr0 = wrow + grp, lr1 = lr0 + 8;
#pragma unroll
            for (int tn = 0; tn < 4; tn++) {
                int lc0 = wc + tn * 8 + qid * 2;
                int lc1 = lc0 + 1;
                if (lc0 > lr0) s[tn][0] = -1e30f;
                if (lc1 > lr0) s[tn][1] = -1e30f;
                if (lc0 > lr1) s[tn][2] = -1e30f;
                if (lc1 > lr1) s[tn][3] = -1e30f;
            }
        }

        float rm0 = -1e30f, rm1 = -1e30f;
#pragma unroll
        for (int tn = 0; tn < 4; tn++) {
            rm0 = fmaxf(rm0, fmaxf(s[tn][0], s[tn][1]));
            rm1 = fmaxf(rm1, fmaxf(s[tn][2], s[tn][3]));
        }
        rm0 = fmaxf(rm0, __shfl_xor_sync(0xffffffffu, rm0, 1));
        rm0 = fmaxf(rm0, __shfl_xor_sync(0xffffffffu, rm0, 2));
        rm1 = fmaxf(rm1, __shfl_xor_sync(0xffffffffu, rm1, 1));
        rm1 = fmaxf(rm1, __shfl_xor_sync(0xffffffffu, rm1, 2));
        if (qid == 0) {
            red_max[wcol * 64 + wrow + grp]     = rm0;
            red_max[wcol * 64 + wrow + grp + 8] = rm1;
        }
        __syncthreads();
        float om0 = red_max[(wcol ^ 1) * 64 + wrow + grp];
        float om1 = red_max[(wcol ^ 1) * 64 + wrow + grp + 8];
        float mn0 = fmaxf(m0, fmaxf(rm0, om0));
        float mn1 = fmaxf(m1, fmaxf(rm1, om1));
        float sc0 = __expf(m0 - mn0);
        float sc1 = __expf(m1 - mn1);

        float rs0 = 0.0f, rs1 = 0.0f;
#pragma unroll
        for (int tn = 0; tn < 4; tn++) {
            s[tn][0] = __expf(s[tn][0] - mn0);
            s[tn][1] = __expf(s[tn][1] - mn0);
            s[tn][2] = __expf(s[tn][2] - mn1);
            s[tn][3] = __expf(s[tn][3] - mn1);
            rs0 += s[tn][0] + s[tn][1];
            rs1 += s[tn][2] + s[tn][3];
            *(float2*)&Ps[(wrow + grp)     * APSTR + wc + tn * 8 + qid * 2] =
                make_float2(s[tn][0], s[tn][1]);
            *(float2*)&Ps[(wrow + grp + 8) * APSTR + wc + tn * 8 + qid * 2] =
                make_float2(s[tn][2], s[tn][3]);
        }
        rs0 += __shfl_xor_sync(0xffffffffu, rs0, 1);
        rs0 += __shfl_xor_sync(0xffffffffu, rs0, 2);
        rs1 += __shfl_xor_sync(0xffffffffu, rs1, 1);
        rs1 += __shfl_xor_sync(0xffffffffu, rs1, 2);
        if (qid == 0) {
            red_sum[wcol * 64 + wrow + grp]     = rs0;
            red_sum[wcol * 64 + wrow + grp + 8] = rs1;
        }
        __syncthreads();
        float os0 = red_sum[(wcol ^ 1) * 64 + wrow + grp];
        float os1 = red_sum[(wcol ^ 1) * 64 + wrow + grp + 8];
        l0 = l0 * sc0 + rs0 + os0;
        l1 = l1 * sc1 + rs1 + os1;
        m0 = mn0;
        m1 = mn1;
#pragma unroll
        for (int tn = 0; tn < 8; tn++) {
            acc[tn][0] *= sc0; acc[tn][1] *= sc0;
            acc[tn][2] *= sc1; acc[tn][3] *= sc1;
        }

#pragma unroll 2
        for (int kk = 0; kk < 64; kk += 8) {
            float p0 = Ps[(wrow + grp)     * APSTR + kk + qid];
            float p1 = Ps[(wrow + grp + 8) * APSTR + kk + qid];
            float p2 = Ps[(wrow + grp)     * APSTR + kk + qid + 4];
            float p3 = Ps[(wrow + grp + 8) * APSTR + kk + qid + 4];
            unsigned ph0, pl0, ph1, pl1, ph2, pl2, ph3, pl3;
            tf32_split(p0, ph0, pl0);
            tf32_split(p1, ph1, pl1);
            tf32_split(p2, ph2, pl2);
            tf32_split(p3, ph3, pl3);
#pragma unroll
            for (int tn = 0; tn < 8; tn++) {
                uint2 b0 = *(const uint2*)&Vhl[(kk + qid)     * ASTR + 2 * (wd + tn * 8 + grp)];
                uint2 b1 = *(const uint2*)&Vhl[(kk + qid + 4) * ASTR + 2 * (wd + tn * 8 + grp)];
                mma_tf32(acc[tn], ph0, ph1, ph2, ph3, b0.x, b1.x);
                mma_tf32(acc[tn], ph0, ph1, ph2, ph3, b0.y, b1.y);
                mma_tf32(acc[tn], pl0, pl1, pl2, pl3, b0.x, b1.x);
            }
        }
    }

    float il0 = 1.0f / l0, il1 = 1.0f / l1;
    int row0 = qt * 64 + wrow + grp;
    int row1 = row0 + 8;
#pragma unroll
    for (int tn = 0; tn < 8; tn++) {
        int col = h * HD + wd + tn * 8 + qid * 2;
        *(float2*)&CTX[(size_t)row0 * (NHQ * HD) + col] =
            make_float2(acc[tn][0] * il0, acc[tn][1] * il0);
        *(float2*)&CTX[(size_t)row1 * (NHQ * HD) + col] =
            make_float2(acc[tn][2] * il1, acc[tn][3] * il1);
    }
}

// ============================================================================
// launch
// ============================================================================
extern "C" void kernel_launch(void* const* d_in, const int* in_sizes, int n_in,
                              void* d_out, int out_size)
{
    const float* X  = (const float*)d_in[0];
    const float* Wq = (const float*)d_in[1];
    const float* bq = (const float*)d_in[2];
    const float* Wk = (const float*)d_in[3];
    const float* bk = (const float*)d_in[4];
    const float* Wv = (const float*)d_in[5];
    const float* bv = (const float*)d_in[6];
    const float* Wo = (const float*)d_in[7];
    const float* bo = (const float*)d_in[8];
    float* out = (float*)d_out;

    float *Qd, *Kd, *Vd, *CTXd, *CSd, *SNd;
    cudaGetSymbolAddress((void**)&Qd,   g_Q);
    cudaGetSymbolAddress((void**)&Kd,   g_K);
    cudaGetSymbolAddress((void**)&Vd,   g_V);
    cudaGetSymbolAddress((void**)&CTXd, g_CTX);
    cudaGetSymbolAddress((void**)&CSd,  g_cs);
    cudaGetSymbolAddress((void**)&SNd,  g_sn);
    __nv_bfloat16 *Xhi, *Xlo, *CThi, *CTlo, *Wqh, *Wql, *Wkh, *Wkl, *Wvh, *Wvl, *Woh, *Wol;
    cudaGetSymbolAddress((void**)&Xhi,  g_Xhi);
    cudaGetSymbolAddress((void**)&Xlo,  g_Xlo);
    cudaGetSymbolAddress((void**)&CThi, g_CTXhi);
    cudaGetSymbolAddress((void**)&CTlo, g_CTXlo);
    cudaGetSymbolAddress((void**)&Wqh,  g_WqhiT);
    cudaGetSymbolAddress((void**)&Wql,  g_WqloT);
    cudaGetSymbolAddress((void**)&Wkh,  g_WkhiT);
    cudaGetSymbolAddress((void**)&Wkl,  g_WkloT);
    cudaGetSymbolAddress((void**)&Wvh,  g_WvhiT);
    cudaGetSymbolAddress((void**)&Wvl,  g_WvloT);
    cudaGetSymbolAddress((void**)&Woh,  g_WohiT);
    cudaGetSymbolAddress((void**)&Wol,  g_WoloT);

    const int gemm_smem = 2 * GSTAGE * (int)sizeof(unsigned);  // 81920 B
    cudaFuncSetAttribute(qkv_proj_kernel,
                         cudaFuncAttributeMaxDynamicSharedMemorySize, gemm_smem);
    cudaFuncSetAttribute(out_proj_kernel,
                         cudaFuncAttributeMaxDynamicSharedMemorySize, gemm_smem);

    // RoPE table
    rope_table_kernel<<<(S_LEN * 64 + 255) / 256, 256>>>(CSd, SNd);

    // Pre-split operands: X plain; weights transpose-split to [N][K]
    {
        int n4 = S_LEN * HID / 4;
        split_plain_kernel<<<(n4 + 255) / 256, 256>>>(X, Xhi, Xlo, n4);
        dim3 gq(NHQ * HD / 32, HID / 32);
        transpose_split_kernel<<<gq, 256>>>(Wq, Wqh, Wql, HID, NHQ * HD);
        dim3 gk(NHKV * HD / 32, HID / 32);
        transpose_split_kernel<<<gk, 256>>>(Wk, Wkh, Wkl, HID, NHKV * HD);
        transpose_split_kernel<<<gk, 256>>>(Wv, Wvh, Wvl, HID, NHKV * HD);
        dim3 go(HID / 32, NHQ * HD / 32);
        transpose_split_kernel<<<go, 256>>>(Wo, Woh, Wol, NHQ * HD, HID);
    }

    // Fused QKV projections (bf16x3 tensor cores)
    qkv_proj_kernel<<<768, 256, gemm_smem>>>(bq, Qd, bk, Kd, bv, Vd);

    // RoPE on K only (Q rope fused into attention load)
    {
        int tk = S_LEN * NHKV * 64;
        rope_kernel<<<(tk + 255) / 256, 256>>>(Kd, CSd, SNd, NHKV);
    }

    // attention (tensor-core, fused Q-RoPE, LPT tile order)
    {
        int smem = (3 * 64 * ASTR) * 4 + (64 * APSTR) * 4 + 2 * 128 * 4;  // 221184 B
        cudaFuncSetAttribute(attn_tc_kernel,
                             cudaFuncAttributeMaxDynamicSharedMemorySize, smem);
        dim3 ga(S_LEN / 64, NHQ);
        attn_tc_kernel<<<ga, 256, smem>>>(Qd, Kd, Vd, CSd, SNd, CTXd);
    }

    // split CTX, then output projection (bf16x3)
    {
        int n4 = S_LEN * HID / 4;
        split_plain_kernel<<<(n4 + 255) / 256, 256>>>(CTXd, CThi, CTlo, n4);
        dim3 go(HID / 128, S_LEN / 128);
        out_proj_kernel<<<go, 256, gemm_smem>>>(bo, out);
    }
}